// round 1
// baseline (speedup 1.0000x reference)
#include <cuda_runtime.h>
#include <math.h>

#define B_  16
#define C_  1024
#define CH_ 512
#define HW_ 4096

#define BM 128
#define BN 128
#define BK 8

// ---------------- scratch (device globals; no allocation allowed) ----------------
__device__ __align__(16) float g_qr[B_ * HW_];       // relu(x . w_qr) logits
__device__ __align__(16) float g_mask[B_ * HW_];     // softmax over hw
__device__ __align__(16) float g_gx[B_ * CH_];       // sum_n relu(x . w_ql)
__device__ __align__(16) float g_avg[B_ * CH_];      // softmax(mean g_x)
__device__ __align__(16) float g_ctx[B_ * CH_];      // context (mask-weighted sum of vr)
__device__ __align__(16) float g_spatial[B_ * CH_];  // sigmoid(layernorm(context))
__device__ __align__(16) float g_chattn[B_ * HW_];   // sigmoid(channel logits)
// per-tile GEMM partials (deterministic reduction, no atomics)
__device__ __align__(16) float g_part_m[B_ * 4 * 32 * BM];   // modes 0/1: (b, mtile, ntile, row)
__device__ __align__(16) float g_part_n[B_ * 32 * 4 * BN];   // mode 2:   (b, ntile, mtile, col)

// ---------------- block reduction helpers ----------------
template <int NW>
__device__ __forceinline__ float blockSum(float v, float* sh, float* bc) {
#pragma unroll
    for (int o = 16; o > 0; o >>= 1) v += __shfl_xor_sync(0xffffffffu, v, o);
    int t = threadIdx.x;
    if ((t & 31) == 0) sh[t >> 5] = v;
    __syncthreads();
    if (t < 32) {
        float w = (t < NW) ? sh[t] : 0.f;
#pragma unroll
        for (int o = 16; o > 0; o >>= 1) w += __shfl_xor_sync(0xffffffffu, w, o);
        if (t == 0) *bc = w;
    }
    __syncthreads();
    return *bc;
}

template <int NW>
__device__ __forceinline__ float blockMax(float v, float* sh, float* bc) {
#pragma unroll
    for (int o = 16; o > 0; o >>= 1) v = fmaxf(v, __shfl_xor_sync(0xffffffffu, v, o));
    int t = threadIdx.x;
    if ((t & 31) == 0) sh[t >> 5] = v;
    __syncthreads();
    if (t < 32) {
        float w = (t < NW) ? sh[t] : -3.4e38f;
#pragma unroll
        for (int o = 16; o > 0; o >>= 1) w = fmaxf(w, __shfl_xor_sync(0xffffffffu, w, o));
        if (t == 0) *bc = w;
    }
    __syncthreads();
    return *bc;
}

// ---------------- 1-channel GEMV for mask logits ----------------
__global__ void qr_gemv(const float* __restrict__ x, const float* __restrict__ wqr) {
    const int b = blockIdx.y;
    const int n = blockIdx.x * 256 + threadIdx.x;
    const float* xp = x + (size_t)b * C_ * HW_ + n;
    float a0 = 0.f, a1 = 0.f, a2 = 0.f, a3 = 0.f;
#pragma unroll 4
    for (int c = 0; c < C_; c += 4) {
        a0 = fmaf(wqr[c + 0], xp[(size_t)(c + 0) * HW_], a0);
        a1 = fmaf(wqr[c + 1], xp[(size_t)(c + 1) * HW_], a1);
        a2 = fmaf(wqr[c + 2], xp[(size_t)(c + 2) * HW_], a2);
        a3 = fmaf(wqr[c + 3], xp[(size_t)(c + 3) * HW_], a3);
    }
    g_qr[b * HW_ + n] = fmaxf((a0 + a1) + (a2 + a3), 0.f);
}

// ---------------- softmax over hw (mask) : 16 blocks x 1024 ----------------
__global__ void softmax_hw() {
    __shared__ float sh[32];
    __shared__ float bc;
    const int b = blockIdx.x, t = threadIdx.x;
    const float* q = g_qr + b * HW_;
    float v[4];
#pragma unroll
    for (int j = 0; j < 4; j++) v[j] = q[t + j * 1024];
    float m = fmaxf(fmaxf(v[0], v[1]), fmaxf(v[2], v[3]));
    const float bm = blockMax<32>(m, sh, &bc);
    float e[4], s = 0.f;
#pragma unroll
    for (int j = 0; j < 4; j++) { e[j] = __expf(v[j] - bm); s += e[j]; }
    const float bs = blockSum<32>(s, sh, &bc);
    const float inv = 1.f / bs;
#pragma unroll
    for (int j = 0; j < 4; j++) g_mask[b * HW_ + t + j * 1024] = e[j] * inv;
}

// ---------------- softmax over ch of mean(g_x) : 16 blocks x 512 ----------------
__global__ void softmax_avg() {
    __shared__ float sh[16];
    __shared__ float bc;
    const int b = blockIdx.x, t = threadIdx.x;
    const float v = g_gx[b * CH_ + t] * (1.f / (float)HW_);
    const float bm = blockMax<16>(v, sh, &bc);
    const float e = __expf(v - bm);
    const float bs = blockSum<16>(e, sh, &bc);
    g_avg[b * CH_ + t] = e / bs;
}

// ---------------- layernorm(context) -> sigmoid : 16 blocks x 512 ----------------
__global__ void ln_sig() {
    __shared__ float sh[16];
    __shared__ float bc;
    const int b = blockIdx.x, t = threadIdx.x;
    const float c = g_ctx[b * CH_ + t];
    const float mean = blockSum<16>(c, sh, &bc) * (1.f / (float)CH_);
    const float d = c - mean;
    const float var = blockSum<16>(d * d, sh, &bc) * (1.f / (float)CH_);
    const float z = d * rsqrtf(var + 1e-5f);
    g_spatial[b * CH_ + t] = 1.f / (1.f + __expf(-z));
}

// ---------------- fused GEMM + reduction epilogue ----------------
// MODE 0: out[b,m] = sum_n relu(acc)            (w = w_ql)  -> g_part_m
// MODE 1: out[b,m] = sum_n mask[b,n]*relu(acc)  (w = w_vr)  -> g_part_m
// MODE 2: out[b,n] = sum_m avg[b,m]*relu(acc)   (w = w_vl)  -> g_part_n
template <int MODE>
__global__ __launch_bounds__(256, 2) void gemm_reduce(const float* __restrict__ x,
                                                      const float* __restrict__ w) {
    __shared__ float As[2][BK][BM];
    __shared__ float Bs[2][BK][BN];
    const int b  = blockIdx.z;
    const int m0 = blockIdx.y * BM;
    const int n0 = blockIdx.x * BN;
    const float* X = x + (size_t)b * C_ * HW_;
    const int tid = threadIdx.x;
    const int tx = tid & 15;
    const int ty = tid >> 4;

    const int a_row = tid >> 1;           // 0..127
    const int a_col = (tid & 1) * 4;      // 0 or 4
    const int b_row = tid >> 5;           // 0..7
    const int b_col = (tid & 31) * 4;     // 0..124

    float4 aload = *(const float4*)(w + (size_t)(m0 + a_row) * C_ + a_col);
    float4 bload = *(const float4*)(X + (size_t)b_row * HW_ + n0 + b_col);
    As[0][a_col + 0][a_row] = aload.x;
    As[0][a_col + 1][a_row] = aload.y;
    As[0][a_col + 2][a_row] = aload.z;
    As[0][a_col + 3][a_row] = aload.w;
    *(float4*)&Bs[0][b_row][b_col] = bload;
    __syncthreads();

    float acc[8][8];
#pragma unroll
    for (int i = 0; i < 8; i++)
#pragma unroll
        for (int j = 0; j < 8; j++) acc[i][j] = 0.f;

    int buf = 0;
    for (int k0 = 0; k0 < C_; k0 += BK) {
        const int kn = k0 + BK;
        if (kn < C_) {
            aload = *(const float4*)(w + (size_t)(m0 + a_row) * C_ + kn + a_col);
            bload = *(const float4*)(X + (size_t)(kn + b_row) * HW_ + n0 + b_col);
        }
#pragma unroll
        for (int kk = 0; kk < BK; kk++) {
            float areg[8], breg[8];
            *(float4*)(&areg[0]) = *(const float4*)(&As[buf][kk][ty * 8]);
            *(float4*)(&areg[4]) = *(const float4*)(&As[buf][kk][ty * 8 + 4]);
            *(float4*)(&breg[0]) = *(const float4*)(&Bs[buf][kk][tx * 8]);
            *(float4*)(&breg[4]) = *(const float4*)(&Bs[buf][kk][tx * 8 + 4]);
#pragma unroll
            for (int i = 0; i < 8; i++)
#pragma unroll
                for (int j = 0; j < 8; j++)
                    acc[i][j] = fmaf(areg[i], breg[j], acc[i][j]);
        }
        if (kn < C_) {
            As[buf ^ 1][a_col + 0][a_row] = aload.x;
            As[buf ^ 1][a_col + 1][a_row] = aload.y;
            As[buf ^ 1][a_col + 2][a_row] = aload.z;
            As[buf ^ 1][a_col + 3][a_row] = aload.w;
            *(float4*)&Bs[buf ^ 1][b_row][b_col] = bload;
            __syncthreads();
            buf ^= 1;
        }
    }

    __syncthreads();                 // done reading smem; reuse As as reduction scratch
    float* red = &As[0][0][0];       // 128*16 floats = 8KB

    if (MODE == 0 || MODE == 1) {
        float msk[8];
        if (MODE == 1) {
#pragma unroll
            for (int j = 0; j < 8; j++) msk[j] = g_mask[b * HW_ + n0 + tx * 8 + j];
        }
#pragma unroll
        for (int i = 0; i < 8; i++) {
            float s = 0.f;
#pragma unroll
            for (int j = 0; j < 8; j++) {
                const float v = fmaxf(acc[i][j], 0.f);
                s += (MODE == 1) ? v * msk[j] : v;
            }
            red[(ty * 8 + i) * 16 + tx] = s;
        }
        __syncthreads();
        if (tid < BM) {
            float s = 0.f;
#pragma unroll
            for (int t = 0; t < 16; t++) s += red[tid * 16 + t];
            g_part_m[(((size_t)b * 4 + blockIdx.y) * 32 + blockIdx.x) * BM + tid] = s;
        }
    } else {
        float av[8];
#pragma unroll
        for (int i = 0; i < 8; i++) av[i] = g_avg[b * CH_ + m0 + ty * 8 + i];
#pragma unroll
        for (int j = 0; j < 8; j++) {
            float s = 0.f;
#pragma unroll
            for (int i = 0; i < 8; i++) s += av[i] * fmaxf(acc[i][j], 0.f);
            red[(tx * 8 + j) * 16 + ty] = s;
        }
        __syncthreads();
        if (tid < BN) {
            float s = 0.f;
#pragma unroll
            for (int t = 0; t < 16; t++) s += red[tid * 16 + t];
            g_part_n[(((size_t)b * 32 + blockIdx.x) * 4 + blockIdx.y) * BN + tid] = s;
        }
    }
}

// deterministic reduce of g_part_m over the 32 n-tiles. dest 0 -> g_gx, 1 -> g_ctx
__global__ void reduce_m(int dest) {
    const int i = blockIdx.x * blockDim.x + threadIdx.x;  // 8192
    const int b = i >> 9;
    const int m = i & 511;
    const int my = m >> 7, row = m & 127;
    const float* p = g_part_m + (((size_t)b * 4 + my) * 32) * BM + row;
    float s = 0.f;
#pragma unroll 8
    for (int nt = 0; nt < 32; nt++) s += p[(size_t)nt * BM];
    if (dest == 0) g_gx[i] = s; else g_ctx[i] = s;
}

// deterministic reduce of g_part_n over the 4 m-tiles, fused sigmoid -> g_chattn
__global__ void reduce_n() {
    const int i = blockIdx.x * blockDim.x + threadIdx.x;  // 65536
    const int b = i >> 12;
    const int n = i & 4095;
    const int nx = n >> 7, col = n & 127;
    const float* p = g_part_n + (((size_t)b * 32 + nx) * 4) * BN + col;
    float s = 0.f;
#pragma unroll
    for (int mt = 0; mt < 4; mt++) s += p[(size_t)mt * BN];
    g_chattn[i] = 1.f / (1.f + __expf(-s));
}

// ---------------- final elementwise combine ----------------
__global__ void combine(const float* __restrict__ x, float* __restrict__ out) {
    const size_t i = (size_t)blockIdx.x * blockDim.x + threadIdx.x;  // float4 index, 16M total
    const int n4 = (int)(i & 1023);
    const int c  = (int)((i >> 10) & 1023);
    const int b  = (int)(i >> 20);
    const float4 xv = ((const float4*)x)[i];
    const float4 ch = ((const float4*)g_chattn)[(size_t)b * 1024 + n4];
    const float sp = g_spatial[b * CH_ + (c & (CH_ - 1))];
    float4 o;
    if (c < CH_) {
        o.x = fmaf(xv.x, sp * ch.x, xv.x);
        o.y = fmaf(xv.y, sp * ch.y, xv.y);
        o.z = fmaf(xv.z, sp * ch.z, xv.z);
        o.w = fmaf(xv.w, sp * ch.w, xv.w);
    } else {
        o.x = fmaf(xv.x, sp + ch.x, xv.x);
        o.y = fmaf(xv.y, sp + ch.y, xv.y);
        o.z = fmaf(xv.z, sp + ch.z, xv.z);
        o.w = fmaf(xv.w, sp + ch.w, xv.w);
    }
    ((float4*)out)[i] = o;
}

// ---------------- launch ----------------
extern "C" void kernel_launch(void* const* d_in, const int* in_sizes, int n_in,
                              void* d_out, int out_size) {
    const float* x    = (const float*)d_in[0];
    const float* w_qr = (const float*)d_in[1];
    const float* w_vr = (const float*)d_in[2];
    const float* w_ql = (const float*)d_in[3];
    const float* w_vl = (const float*)d_in[4];
    float* out = (float*)d_out;

    const dim3 ggrid(HW_ / BN, CH_ / BM, B_);  // 32 x 4 x 16

    qr_gemv<<<dim3(HW_ / 256, B_), 256>>>(x, w_qr);
    softmax_hw<<<B_, 1024>>>();

    gemm_reduce<0><<<ggrid, 256>>>(x, w_ql);
    reduce_m<<<32, 256>>>(0);
    softmax_avg<<<B_, 512>>>();

    gemm_reduce<1><<<ggrid, 256>>>(x, w_vr);
    reduce_m<<<32, 256>>>(1);
    ln_sig<<<B_, 512>>>();

    gemm_reduce<2><<<ggrid, 256>>>(x, w_vl);
    reduce_n<<<256, 256>>>();

    combine<<<(B_ * C_ * HW_ / 4) / 256, 256>>>(x, out);
}

// round 4
// speedup vs baseline: 4.6045x; 4.6045x over previous
#include <cuda_runtime.h>
#include <cuda_bf16.h>
#include <stdint.h>
#include <math.h>

#define B_  16
#define C_  1024
#define CH_ 512
#define HW_ 4096

// ---------------- device scratch ----------------
__device__ __align__(16) __nv_bfloat16 g_wbf[1536 * 1024];              // stacked [ql;vr;vl] bf16
__device__ __align__(16) __nv_bfloat16 g_xbf[(size_t)B_ * HW_ * 1024];  // xT[b][n][k] bf16
__device__ __align__(16) float g_qr[B_ * HW_];
__device__ __align__(16) float g_mask[B_ * HW_];
__device__ __align__(16) float g_gx[B_ * CH_];
__device__ __align__(16) float g_avg[B_ * CH_];
__device__ __align__(16) float g_ctx[B_ * CH_];
__device__ __align__(16) float g_spatial[B_ * CH_];
__device__ __align__(16) float g_chattn[B_ * HW_];
__device__ __align__(16) float g_part_m[B_ * 8 * 16 * 128];  // (b, mtile8, ntile16, row128)
__device__ __align__(16) float g_part_n[B_ * 16 * 4 * 256];  // (b, ntile16, mtile4, col256)

// ---------------- helpers ----------------
__device__ __forceinline__ uint32_t s2u(const void* p) {
    uint32_t a;
    asm("{ .reg .u64 t; cvta.to.shared.u64 t, %1; cvt.u32.u64 %0, t; }" : "=r"(a) : "l"(p));
    return a;
}
__device__ __forceinline__ void cp16(uint32_t dst, const void* src) {
    asm volatile("cp.async.cg.shared.global [%0], [%1], 16;" :: "r"(dst), "l"(src) : "memory");
}
#define CP_COMMIT() asm volatile("cp.async.commit_group;" ::: "memory")
#define CP_WAIT(n)  asm volatile("cp.async.wait_group %0;" :: "n"(n) : "memory")

__device__ __forceinline__ void mma16816(float* d, uint32_t a0, uint32_t a1, uint32_t a2,
                                         uint32_t a3, uint32_t b0, uint32_t b1) {
    asm volatile(
        "mma.sync.aligned.m16n8k16.row.col.f32.bf16.bf16.f32 "
        "{%0,%1,%2,%3}, {%4,%5,%6,%7}, {%8,%9}, {%0,%1,%2,%3};"
        : "+f"(d[0]), "+f"(d[1]), "+f"(d[2]), "+f"(d[3])
        : "r"(a0), "r"(a1), "r"(a2), "r"(a3), "r"(b0), "r"(b1));
}

// ---------------- conversion kernels ----------------
__global__ void convert_w(const float* __restrict__ wql, const float* __restrict__ wvr,
                          const float* __restrict__ wvl) {
    const int i = blockIdx.x * 512 + threadIdx.x;  // 786432 pairs
    const int m = i >> 9;
    const int k = (i & 511) * 2;
    const float* src = (m < 512) ? (wql + (size_t)m * 1024)
                                 : ((m < 1024) ? (wvr + (size_t)(m - 512) * 1024)
                                               : (wvl + (size_t)(m - 1024) * 1024));
    __nv_bfloat162 h = __floats2bfloat162_rn(src[k], src[k + 1]);
    ((uint32_t*)g_wbf)[i] = *reinterpret_cast<uint32_t*>(&h);
}

// x[b][c][n] fp32 -> xT[b][n][c] bf16.  tile: c=128, n=32
__global__ void transpose_x(const float* __restrict__ x) {
    __shared__ float s[32][129];
    const int tid = threadIdx.x;
    const int n0 = blockIdx.x * 32, c0 = blockIdx.y * 128, b = blockIdx.z;
#pragma unroll
    for (int r = 0; r < 16; r++) {
        const int ci = (tid >> 5) + r * 8;
        const int ni = tid & 31;
        s[ni][ci] = x[((size_t)(b * C_ + c0 + ci)) * HW_ + n0 + ni];
    }
    __syncthreads();
#pragma unroll
    for (int r = 0; r < 8; r++) {
        const int ni = (tid >> 6) + r * 4;
        const int u = tid & 63;
        __nv_bfloat162 h = __floats2bfloat162_rn(s[ni][u * 2], s[ni][u * 2 + 1]);
        ((uint32_t*)g_xbf)[((size_t)(b * HW_ + n0 + ni)) * 512 + (c0 >> 1) + u] =
            *reinterpret_cast<uint32_t*>(&h);
    }
}

// ---------------- 1-channel GEMV for mask logits (fp32 path, accuracy) ----------------
__global__ void qr_gemv(const float* __restrict__ x, const float* __restrict__ wqr) {
    const int b = blockIdx.y;
    const int n = blockIdx.x * 256 + threadIdx.x;
    const float* xp = x + (size_t)b * C_ * HW_ + n;
    float a0 = 0.f, a1 = 0.f, a2 = 0.f, a3 = 0.f;
#pragma unroll 4
    for (int c = 0; c < C_; c += 4) {
        a0 = fmaf(wqr[c + 0], xp[(size_t)(c + 0) * HW_], a0);
        a1 = fmaf(wqr[c + 1], xp[(size_t)(c + 1) * HW_], a1);
        a2 = fmaf(wqr[c + 2], xp[(size_t)(c + 2) * HW_], a2);
        a3 = fmaf(wqr[c + 3], xp[(size_t)(c + 3) * HW_], a3);
    }
    g_qr[b * HW_ + n] = fmaxf((a0 + a1) + (a2 + a3), 0.f);
}

// ---------------- small reductions ----------------
template <int NW>
__device__ __forceinline__ float blockSum(float v, float* sh, float* bc) {
#pragma unroll
    for (int o = 16; o > 0; o >>= 1) v += __shfl_xor_sync(0xffffffffu, v, o);
    int t = threadIdx.x;
    if ((t & 31) == 0) sh[t >> 5] = v;
    __syncthreads();
    if (t < 32) {
        float w = (t < NW) ? sh[t] : 0.f;
#pragma unroll
        for (int o = 16; o > 0; o >>= 1) w += __shfl_xor_sync(0xffffffffu, w, o);
        if (t == 0) *bc = w;
    }
    __syncthreads();
    return *bc;
}
template <int NW>
__device__ __forceinline__ float blockMax(float v, float* sh, float* bc) {
#pragma unroll
    for (int o = 16; o > 0; o >>= 1) v = fmaxf(v, __shfl_xor_sync(0xffffffffu, v, o));
    int t = threadIdx.x;
    if ((t & 31) == 0) sh[t >> 5] = v;
    __syncthreads();
    if (t < 32) {
        float w = (t < NW) ? sh[t] : -3.4e38f;
#pragma unroll
        for (int o = 16; o > 0; o >>= 1) w = fmaxf(w, __shfl_xor_sync(0xffffffffu, w, o));
        if (t == 0) *bc = w;
    }
    __syncthreads();
    return *bc;
}

__global__ void softmax_hw() {
    __shared__ float sh[32];
    __shared__ float bc;
    const int b = blockIdx.x, t = threadIdx.x;
    const float* q = g_qr + b * HW_;
    float v[4];
#pragma unroll
    for (int j = 0; j < 4; j++) v[j] = q[t + j * 1024];
    float m = fmaxf(fmaxf(v[0], v[1]), fmaxf(v[2], v[3]));
    const float bm = blockMax<32>(m, sh, &bc);
    float e[4], s = 0.f;
#pragma unroll
    for (int j = 0; j < 4; j++) { e[j] = __expf(v[j] - bm); s += e[j]; }
    const float bs = blockSum<32>(s, sh, &bc);
    const float inv = 1.f / bs;
#pragma unroll
    for (int j = 0; j < 4; j++) g_mask[b * HW_ + t + j * 1024] = e[j] * inv;
}

__global__ void softmax_avg() {
    __shared__ float sh[16];
    __shared__ float bc;
    const int b = blockIdx.x, t = threadIdx.x;
    const float v = g_gx[b * CH_ + t] * (1.f / (float)HW_);
    const float bm = blockMax<16>(v, sh, &bc);
    const float e = __expf(v - bm);
    const float bs = blockSum<16>(e, sh, &bc);
    g_avg[b * CH_ + t] = e / bs;
}

__global__ void ln_sig() {
    __shared__ float sh[16];
    __shared__ float bc;
    const int b = blockIdx.x, t = threadIdx.x;
    const float c = g_ctx[b * CH_ + t];
    const float mean = blockSum<16>(c, sh, &bc) * (1.f / (float)CH_);
    const float d = c - mean;
    const float var = blockSum<16>(d * d, sh, &bc) * (1.f / (float)CH_);
    const float z = d * rsqrtf(var + 1e-5f);
    g_spatial[b * CH_ + t] = 1.f / (1.f + __expf(-z));
}

// ---------------- HMMA GEMM with fused reduction epilogues ----------------
// Block tile M=128, N=256, K=32 (double-buffered). 8 warps: warp tile 64x64.
// PHASE 0: mtb 0..7 over stacked [ql;vr]: mtb<4 plain row sums; mtb>=4 mask-weighted.
// PHASE 1: mtb 0..3 over vl: avg-weighted col sums.
// smem: As[2][128][40] bf16 (20480B) + Bs[2][256][40] bf16 (40960B) = 61440B.
#define SMEM_GEMM 61440

__device__ __forceinline__ void load_tile(uint32_t sA, uint32_t sB,
                                          const __nv_bfloat16* __restrict__ Wp,
                                          const __nv_bfloat16* __restrict__ Xp,
                                          int kb, int buf, int lrow, int lseg) {
#pragma unroll
    for (int i = 0; i < 2; i++) {
        const int row = lrow + i * 64;
        cp16(sA + (uint32_t)(buf * 5120 + row * 40 + lseg * 8) * 2u,
             Wp + (size_t)row * 1024 + kb * 32 + lseg * 8);
    }
#pragma unroll
    for (int i = 0; i < 4; i++) {
        const int row = lrow + i * 64;
        cp16(sB + (uint32_t)(buf * 10240 + row * 40 + lseg * 8) * 2u,
             Xp + (size_t)row * 1024 + kb * 32 + lseg * 8);
    }
    CP_COMMIT();
}

template <int PHASE>
__global__ __launch_bounds__(256, 1) void hmma_gemm() {
    extern __shared__ char dsm[];
    __nv_bfloat16* As = (__nv_bfloat16*)dsm;
    __nv_bfloat16* Bs = (__nv_bfloat16*)(dsm + 20480);
    const uint32_t sA = s2u(dsm), sB = sA + 20480;

    const int tid = threadIdx.x, lid = tid & 31, wid = tid >> 5;
    const int wm = wid & 1, wn = wid >> 1;
    const int g = lid >> 2, q = lid & 3;
    const int b = blockIdx.z, ntb = blockIdx.x, mtb = blockIdx.y;
    const int n0 = ntb * 256;
    const int m0 = (PHASE == 0 ? 0 : 1024) + mtb * 128;
    const __nv_bfloat16* Wp = g_wbf + (size_t)m0 * 1024;
    const __nv_bfloat16* Xp = g_xbf + ((size_t)b * HW_ + n0) * 1024;

    const int lrow = tid >> 2, lseg = tid & 3;

    float acc[4][8][4];
#pragma unroll
    for (int mt = 0; mt < 4; mt++)
#pragma unroll
        for (int nt = 0; nt < 8; nt++)
#pragma unroll
            for (int e = 0; e < 4; e++) acc[mt][nt][e] = 0.f;

    load_tile(sA, sB, Wp, Xp, 0, 0, lrow, lseg);

    for (int it = 0; it < 32; ++it) {
        const int buf = it & 1;
        if (it + 1 < 32) {
            load_tile(sA, sB, Wp, Xp, it + 1, buf ^ 1, lrow, lseg);
            CP_WAIT(1);
        } else {
            CP_WAIT(0);
        }
        __syncthreads();

        const __nv_bfloat16* Ab = As + buf * 5120;
        const __nv_bfloat16* Bb = Bs + buf * 10240;
#pragma unroll
        for (int st = 0; st < 2; ++st) {
            const int kk = st * 16 + q * 2;
            uint32_t af[4][4];
#pragma unroll
            for (int mt = 0; mt < 4; mt++) {
                const int r = wm * 64 + mt * 16 + g;
                af[mt][0] = *(const uint32_t*)(Ab + r * 40 + kk);
                af[mt][1] = *(const uint32_t*)(Ab + (r + 8) * 40 + kk);
                af[mt][2] = *(const uint32_t*)(Ab + r * 40 + kk + 8);
                af[mt][3] = *(const uint32_t*)(Ab + (r + 8) * 40 + kk + 8);
            }
            uint32_t bfr[8][2];
#pragma unroll
            for (int nt = 0; nt < 8; nt++) {
                const int c = wn * 64 + nt * 8 + g;
                bfr[nt][0] = *(const uint32_t*)(Bb + c * 40 + kk);
                bfr[nt][1] = *(const uint32_t*)(Bb + c * 40 + kk + 8);
            }
#pragma unroll
            for (int mt = 0; mt < 4; mt++)
#pragma unroll
                for (int nt = 0; nt < 8; nt++)
                    mma16816(acc[mt][nt], af[mt][0], af[mt][1], af[mt][2], af[mt][3],
                             bfr[nt][0], bfr[nt][1]);
        }
        __syncthreads();
    }

    // ---------------- fused reduction epilogue ----------------
    if (PHASE == 0) {
        float* rowred = (float*)dsm;          // [128][4]
        float* mskS = (float*)dsm + 512;      // [256]
        const bool vrm = (mtb >= 4);
        if (vrm) mskS[tid] = g_mask[b * HW_ + n0 + tid];
        __syncthreads();
        float pr[4][2];
#pragma unroll
        for (int mt = 0; mt < 4; mt++) { pr[mt][0] = 0.f; pr[mt][1] = 0.f; }
#pragma unroll
        for (int mt = 0; mt < 4; mt++)
#pragma unroll
            for (int nt = 0; nt < 8; nt++)
#pragma unroll
                for (int rp = 0; rp < 2; rp++)
#pragma unroll
                    for (int e = 0; e < 2; e++) {
                        const float v = fmaxf(acc[mt][nt][rp * 2 + e], 0.f);
                        const int col = wn * 64 + nt * 8 + q * 2 + e;
                        pr[mt][rp] += vrm ? v * mskS[col] : v;
                    }
#pragma unroll
        for (int o = 1; o <= 2; o <<= 1)
#pragma unroll
            for (int mt = 0; mt < 4; mt++)
#pragma unroll
                for (int rp = 0; rp < 2; rp++)
                    pr[mt][rp] += __shfl_xor_sync(0xffffffffu, pr[mt][rp], o);
        if (q == 0) {
#pragma unroll
            for (int mt = 0; mt < 4; mt++)
#pragma unroll
                for (int rp = 0; rp < 2; rp++)
                    rowred[(wm * 64 + mt * 16 + g + rp * 8) * 4 + wn] = pr[mt][rp];
        }
        __syncthreads();
        if (tid < 128) {
            const float s = rowred[tid * 4] + rowred[tid * 4 + 1] +
                            rowred[tid * 4 + 2] + rowred[tid * 4 + 3];
            g_part_m[(((size_t)b * 8 + mtb) * 16 + ntb) * 128 + tid] = s;
        }
    } else {
        float* colred = (float*)dsm;          // [256][2]
        float* avS = (float*)dsm + 512;       // [128]
        if (tid < 128) avS[tid] = g_avg[b * CH_ + mtb * 128 + tid];
        __syncthreads();
        float pc[8][2];
#pragma unroll
        for (int nt = 0; nt < 8; nt++) { pc[nt][0] = 0.f; pc[nt][1] = 0.f; }
#pragma unroll
        for (int mt = 0; mt < 4; mt++)
#pragma unroll
            for (int rp = 0; rp < 2; rp++) {
                const float av = avS[wm * 64 + mt * 16 + g + rp * 8];
#pragma unroll
                for (int nt = 0; nt < 8; nt++)
#pragma unroll
                    for (int e = 0; e < 2; e++)
                        pc[nt][e] += av * fmaxf(acc[mt][nt][rp * 2 + e], 0.f);
            }
#pragma unroll
        for (int o = 4; o <= 16; o <<= 1)
#pragma unroll
            for (int nt = 0; nt < 8; nt++)
#pragma unroll
                for (int e = 0; e < 2; e++)
                    pc[nt][e] += __shfl_xor_sync(0xffffffffu, pc[nt][e], o);
        if (g == 0) {
#pragma unroll
            for (int nt = 0; nt < 8; nt++)
#pragma unroll
                for (int e = 0; e < 2; e++)
                    colred[(wn * 64 + nt * 8 + q * 2 + e) * 2 + wm] = pc[nt][e];
        }
        __syncthreads();
        const float s = colred[tid * 2] + colred[tid * 2 + 1];
        g_part_n[(((size_t)b * 16 + ntb) * 4 + mtb) * 256 + tid] = s;
    }
}

// ---------------- deterministic partial reductions ----------------
__global__ void reduce_m2() {
    const int i = blockIdx.x * 256 + threadIdx.x;  // 16384
    const int b = i >> 10, m = i & 1023;
    const float* p = g_part_m + (((size_t)b * 8 + (m >> 7)) * 16) * 128 + (m & 127);
    float s = 0.f;
#pragma unroll
    for (int nt = 0; nt < 16; nt++) s += p[nt * 128];
    if (m < 512) g_gx[b * CH_ + m] = s;
    else g_ctx[b * CH_ + m - 512] = s;
}

__global__ void reduce_n2() {
    const int i = blockIdx.x * 256 + threadIdx.x;  // 65536
    const int b = i >> 12, n = i & 4095;
    const float* p = g_part_n + (((size_t)b * 16 + (n >> 8)) * 4) * 256 + (n & 255);
    const float s = p[0] + p[256] + p[512] + p[768];
    g_chattn[i] = 1.f / (1.f + __expf(-s));
}

// ---------------- final elementwise combine ----------------
__global__ void combine(const float* __restrict__ x, float* __restrict__ out) {
    const size_t i = (size_t)blockIdx.x * blockDim.x + threadIdx.x;
    const int n4 = (int)(i & 1023);
    const int c  = (int)((i >> 10) & 1023);
    const int b  = (int)(i >> 20);
    const float4 xv = ((const float4*)x)[i];
    const float4 ch = ((const float4*)g_chattn)[(size_t)b * 1024 + n4];
    const float sp = g_spatial[b * CH_ + (c & (CH_ - 1))];
    float4 o;
    if (c < CH_) {
        o.x = fmaf(xv.x, sp * ch.x, xv.x);
        o.y = fmaf(xv.y, sp * ch.y, xv.y);
        o.z = fmaf(xv.z, sp * ch.z, xv.z);
        o.w = fmaf(xv.w, sp * ch.w, xv.w);
    } else {
        o.x = fmaf(xv.x, sp + ch.x, xv.x);
        o.y = fmaf(xv.y, sp + ch.y, xv.y);
        o.z = fmaf(xv.z, sp + ch.z, xv.z);
        o.w = fmaf(xv.w, sp + ch.w, xv.w);
    }
    ((float4*)out)[i] = o;
}

// ---------------- launch ----------------
extern "C" void kernel_launch(void* const* d_in, const int* in_sizes, int n_in,
                              void* d_out, int out_size) {
    const float* x    = (const float*)d_in[0];
    const float* w_qr = (const float*)d_in[1];
    const float* w_vr = (const float*)d_in[2];
    const float* w_ql = (const float*)d_in[3];
    const float* w_vl = (const float*)d_in[4];
    float* out = (float*)d_out;

    cudaFuncSetAttribute(hmma_gemm<0>, cudaFuncAttributeMaxDynamicSharedMemorySize, SMEM_GEMM);
    cudaFuncSetAttribute(hmma_gemm<1>, cudaFuncAttributeMaxDynamicSharedMemorySize, SMEM_GEMM);

    convert_w<<<1536, 512>>>(w_ql, w_vr, w_vl);
    transpose_x<<<dim3(HW_ / 32, C_ / 128, B_), 256>>>(x);

    qr_gemv<<<dim3(HW_ / 256, B_), 256>>>(x, w_qr);
    softmax_hw<<<B_, 1024>>>();

    hmma_gemm<0><<<dim3(16, 8, B_), 256, SMEM_GEMM>>>();
    reduce_m2<<<64, 256>>>();
    softmax_avg<<<B_, 512>>>();
    ln_sig<<<B_, 512>>>();

    hmma_gemm<1><<<dim3(16, 4, B_), 256, SMEM_GEMM>>>();
    reduce_n2<<<256, 256>>>();

    combine<<<(B_ * C_ * HW_ / 4) / 256, 256>>>(x, out);
}

// round 5
// speedup vs baseline: 4.6252x; 1.0045x over previous
#include <cuda_runtime.h>
#include <cuda_bf16.h>
#include <stdint.h>
#include <math.h>

#define B_  16
#define C_  1024
#define CH_ 512
#define HW_ 4096

// ---------------- device scratch ----------------
__device__ __align__(16) __nv_bfloat16 g_wbf[1536 * 1024];              // stacked [ql;vr;vl] bf16
__device__ __align__(16) __nv_bfloat16 g_xbf[(size_t)B_ * HW_ * 1024];  // xT[b][n][k] bf16
__device__ __align__(16) float g_qrp[B_ * 8 * HW_];  // qr partials per 128-channel block
__device__ __align__(16) float g_mask[B_ * HW_];
__device__ __align__(16) float g_avg[B_ * CH_];
__device__ __align__(16) float g_spatial[B_ * CH_];
__device__ __align__(16) float g_chattn[B_ * HW_];
__device__ __align__(16) float g_part_m[B_ * 8 * 16 * 128];  // (b, mtile8, ntile16, row128)
__device__ __align__(16) float g_part_n[B_ * 16 * 4 * 256];  // (b, ntile16, mtile4, col256)

// ---------------- helpers ----------------
__device__ __forceinline__ uint32_t s2u(const void* p) {
    uint32_t a;
    asm("{ .reg .u64 t; cvta.to.shared.u64 t, %1; cvt.u32.u64 %0, t; }" : "=r"(a) : "l"(p));
    return a;
}
__device__ __forceinline__ void cp16(uint32_t dst, const void* src) {
    asm volatile("cp.async.cg.shared.global [%0], [%1], 16;" :: "r"(dst), "l"(src) : "memory");
}
#define CP_COMMIT() asm volatile("cp.async.commit_group;" ::: "memory")
#define CP_WAIT(n)  asm volatile("cp.async.wait_group %0;" :: "n"(n) : "memory")

__device__ __forceinline__ void mma16816(float* d, uint32_t a0, uint32_t a1, uint32_t a2,
                                         uint32_t a3, uint32_t b0, uint32_t b1) {
    asm volatile(
        "mma.sync.aligned.m16n8k16.row.col.f32.bf16.bf16.f32 "
        "{%0,%1,%2,%3}, {%4,%5,%6,%7}, {%8,%9}, {%0,%1,%2,%3};"
        : "+f"(d[0]), "+f"(d[1]), "+f"(d[2]), "+f"(d[3])
        : "r"(a0), "r"(a1), "r"(a2), "r"(a3), "r"(b0), "r"(b1));
}

// ---------------- conversion kernels ----------------
__global__ void convert_w(const float* __restrict__ wql, const float* __restrict__ wvr,
                          const float* __restrict__ wvl) {
    const int i = blockIdx.x * 512 + threadIdx.x;  // 786432 pairs
    const int m = i >> 9;
    const int k = (i & 511) * 2;
    const float* src = (m < 512) ? (wql + (size_t)m * 1024)
                                 : ((m < 1024) ? (wvr + (size_t)(m - 512) * 1024)
                                               : (wvl + (size_t)(m - 1024) * 1024));
    __nv_bfloat162 h = __floats2bfloat162_rn(src[k], src[k + 1]);
    ((uint32_t*)g_wbf)[i] = *reinterpret_cast<uint32_t*>(&h);
}

// x[b][c][n] fp32 -> xT[b][n][c] bf16, plus fused partial qr dot product.
__global__ void transpose_x(const float* __restrict__ x, const float* __restrict__ wqr) {
    __shared__ float s[32][129];
    const int tid = threadIdx.x;
    const int n0 = blockIdx.x * 32, c0 = blockIdx.y * 128, b = blockIdx.z;
#pragma unroll
    for (int r = 0; r < 16; r++) {
        const int ci = (tid >> 5) + r * 8;
        const int ni = tid & 31;
        s[ni][ci] = x[((size_t)(b * C_ + c0 + ci)) * HW_ + n0 + ni];
    }
    __syncthreads();
#pragma unroll
    for (int r = 0; r < 8; r++) {
        const int ni = (tid >> 6) + r * 4;
        const int u = tid & 63;
        __nv_bfloat162 h = __floats2bfloat162_rn(s[ni][u * 2], s[ni][u * 2 + 1]);
        ((uint32_t*)g_xbf)[((size_t)(b * HW_ + n0 + ni)) * 512 + (c0 >> 1) + u] =
            *reinterpret_cast<uint32_t*>(&h);
    }
    // fused qr partial: 32 n x 8 lane-groups; each group sums 16 channels
    {
        const int ni = tid >> 3, lg = tid & 7;
        float p = 0.f;
#pragma unroll
        for (int r = 0; r < 16; r++) {
            const int ci = lg * 16 + r;
            p = fmaf(wqr[c0 + ci], s[ni][ci], p);
        }
#pragma unroll
        for (int o = 1; o <= 4; o <<= 1) p += __shfl_xor_sync(0xffffffffu, p, o);
        if (lg == 0) g_qrp[((size_t)b * 8 + blockIdx.y) * HW_ + n0 + ni] = p;
    }
}

// ---------------- small reductions ----------------
template <int NW>
__device__ __forceinline__ float blockSum(float v, float* sh, float* bc) {
#pragma unroll
    for (int o = 16; o > 0; o >>= 1) v += __shfl_xor_sync(0xffffffffu, v, o);
    int t = threadIdx.x;
    if ((t & 31) == 0) sh[t >> 5] = v;
    __syncthreads();
    if (t < 32) {
        float w = (t < NW) ? sh[t] : 0.f;
#pragma unroll
        for (int o = 16; o > 0; o >>= 1) w += __shfl_xor_sync(0xffffffffu, w, o);
        if (t == 0) *bc = w;
    }
    __syncthreads();
    return *bc;
}
template <int NW>
__device__ __forceinline__ float blockMax(float v, float* sh, float* bc) {
#pragma unroll
    for (int o = 16; o > 0; o >>= 1) v = fmaxf(v, __shfl_xor_sync(0xffffffffu, v, o));
    int t = threadIdx.x;
    if ((t & 31) == 0) sh[t >> 5] = v;
    __syncthreads();
    if (t < 32) {
        float w = (t < NW) ? sh[t] : -3.4e38f;
#pragma unroll
        for (int o = 16; o > 0; o >>= 1) w = fmaxf(w, __shfl_xor_sync(0xffffffffu, w, o));
        if (t == 0) *bc = w;
    }
    __syncthreads();
    return *bc;
}

// sum qr partials -> relu -> softmax over hw
__global__ void softmax_hw() {
    __shared__ float sh[32];
    __shared__ float bc;
    const int b = blockIdx.x, t = threadIdx.x;
    float v[4];
#pragma unroll
    for (int j = 0; j < 4; j++) {
        const int n = t + j * 1024;
        float s = 0.f;
#pragma unroll
        for (int cb = 0; cb < 8; cb++) s += g_qrp[((size_t)b * 8 + cb) * HW_ + n];
        v[j] = fmaxf(s, 0.f);
    }
    float m = fmaxf(fmaxf(v[0], v[1]), fmaxf(v[2], v[3]));
    const float bm = blockMax<32>(m, sh, &bc);
    float e[4], s = 0.f;
#pragma unroll
    for (int j = 0; j < 4; j++) { e[j] = __expf(v[j] - bm); s += e[j]; }
    const float bs = blockSum<32>(s, sh, &bc);
    const float inv = 1.f / bs;
#pragma unroll
    for (int j = 0; j < 4; j++) g_mask[b * HW_ + t + j * 1024] = e[j] * inv;
}

// fused: reduce part_m -> gx/ctx -> softmax(avg) + layernorm+sigmoid(spatial)
__global__ void fuse_mid() {
    __shared__ float sh[16];
    __shared__ float bc;
    const int b = blockIdx.x, t = threadIdx.x;  // 512 threads
    float s0 = 0.f, s1 = 0.f;
    {
        const int m = t;            // ql rows
        const float* p = g_part_m + (((size_t)b * 8 + (m >> 7)) * 16) * 128 + (m & 127);
#pragma unroll
        for (int nt = 0; nt < 16; nt++) s0 += p[nt * 128];
    }
    {
        const int m = t + 512;      // vr rows
        const float* p = g_part_m + (((size_t)b * 8 + (m >> 7)) * 16) * 128 + (m & 127);
#pragma unroll
        for (int nt = 0; nt < 16; nt++) s1 += p[nt * 128];
    }
    // softmax over s0/HW
    const float v = s0 * (1.f / (float)HW_);
    const float bm = blockMax<16>(v, sh, &bc);
    const float e = __expf(v - bm);
    const float bs = blockSum<16>(e, sh, &bc);
    g_avg[b * CH_ + t] = e / bs;
    // layernorm + sigmoid over s1
    const float mean = blockSum<16>(s1, sh, &bc) * (1.f / (float)CH_);
    const float d = s1 - mean;
    const float var = blockSum<16>(d * d, sh, &bc) * (1.f / (float)CH_);
    const float z = d * rsqrtf(var + 1e-5f);
    g_spatial[b * CH_ + t] = 1.f / (1.f + __expf(-z));
}

// ---------------- HMMA GEMM with fused reduction epilogues ----------------
// Block tile M=128, N=256, K=32 (double-buffered). 16 warps: warp tile 32x64.
// PHASE 0: mtb 0..7 over stacked [ql;vr]: mtb<4 plain row sums; mtb>=4 mask-weighted.
// PHASE 1: mtb 0..3 over vl: avg-weighted col sums.
// smem: As[2][128][40] bf16 (20480B) + Bs[2][256][40] bf16 (40960B) = 61440B.
#define SMEM_GEMM 61440

__device__ __forceinline__ void load_tile(uint32_t sA, uint32_t sB,
                                          const __nv_bfloat16* __restrict__ Wp,
                                          const __nv_bfloat16* __restrict__ Xp,
                                          int kb, int buf, int lrow, int lseg) {
    cp16(sA + (uint32_t)(buf * 5120 + lrow * 40 + lseg * 8) * 2u,
         Wp + (size_t)lrow * 1024 + kb * 32 + lseg * 8);
#pragma unroll
    for (int i = 0; i < 2; i++) {
        const int row = lrow + i * 128;
        cp16(sB + (uint32_t)(buf * 10240 + row * 40 + lseg * 8) * 2u,
             Xp + (size_t)row * 1024 + kb * 32 + lseg * 8);
    }
    CP_COMMIT();
}

template <int PHASE>
__global__ __launch_bounds__(512, 1) void hmma_gemm() {
    extern __shared__ char dsm[];
    __nv_bfloat16* As = (__nv_bfloat16*)dsm;
    __nv_bfloat16* Bs = (__nv_bfloat16*)(dsm + 20480);
    const uint32_t sA = s2u(dsm), sB = sA + 20480;

    const int tid = threadIdx.x, lid = tid & 31, wid = tid >> 5;
    const int wm = wid & 3, wn = wid >> 2;      // 4 x 4 warp grid
    const int g = lid >> 2, q = lid & 3;
    const int b = blockIdx.z, ntb = blockIdx.x, mtb = blockIdx.y;
    const int n0 = ntb * 256;
    const int m0 = (PHASE == 0 ? 0 : 1024) + mtb * 128;
    const __nv_bfloat16* Wp = g_wbf + (size_t)m0 * 1024;
    const __nv_bfloat16* Xp = g_xbf + ((size_t)b * HW_ + n0) * 1024;

    const int lrow = tid >> 2, lseg = tid & 3;  // 128 rows x 4 segs

    float acc[2][8][4];
#pragma unroll
    for (int mt = 0; mt < 2; mt++)
#pragma unroll
        for (int nt = 0; nt < 8; nt++)
#pragma unroll
            for (int e = 0; e < 4; e++) acc[mt][nt][e] = 0.f;

    load_tile(sA, sB, Wp, Xp, 0, 0, lrow, lseg);

    for (int it = 0; it < 32; ++it) {
        const int buf = it & 1;
        if (it + 1 < 32) {
            load_tile(sA, sB, Wp, Xp, it + 1, buf ^ 1, lrow, lseg);
            CP_WAIT(1);
        } else {
            CP_WAIT(0);
        }
        __syncthreads();

        const __nv_bfloat16* Ab = As + buf * 5120;
        const __nv_bfloat16* Bb = Bs + buf * 10240;
#pragma unroll
        for (int st = 0; st < 2; ++st) {
            const int kk = st * 16 + q * 2;
            uint32_t af[2][4];
#pragma unroll
            for (int mt = 0; mt < 2; mt++) {
                const int r = wm * 32 + mt * 16 + g;
                af[mt][0] = *(const uint32_t*)(Ab + r * 40 + kk);
                af[mt][1] = *(const uint32_t*)(Ab + (r + 8) * 40 + kk);
                af[mt][2] = *(const uint32_t*)(Ab + r * 40 + kk + 8);
                af[mt][3] = *(const uint32_t*)(Ab + (r + 8) * 40 + kk + 8);
            }
            uint32_t bfr[8][2];
#pragma unroll
            for (int nt = 0; nt < 8; nt++) {
                const int c = wn * 64 + nt * 8 + g;
                bfr[nt][0] = *(const uint32_t*)(Bb + c * 40 + kk);
                bfr[nt][1] = *(const uint32_t*)(Bb + c * 40 + kk + 8);
            }
#pragma unroll
            for (int mt = 0; mt < 2; mt++)
#pragma unroll
                for (int nt = 0; nt < 8; nt++)
                    mma16816(acc[mt][nt], af[mt][0], af[mt][1], af[mt][2], af[mt][3],
                             bfr[nt][0], bfr[nt][1]);
        }
        __syncthreads();
    }

    // ---------------- fused reduction epilogue ----------------
    if (PHASE == 0) {
        float* rowred = (float*)dsm;            // [128][4]
        float* mskS = (float*)dsm + 1024;       // [256]
        const bool vrm = (mtb >= 4);
        if (vrm && tid < 256) mskS[tid] = g_mask[b * HW_ + n0 + tid];
        __syncthreads();
        float pr[2][2];
#pragma unroll
        for (int mt = 0; mt < 2; mt++) { pr[mt][0] = 0.f; pr[mt][1] = 0.f; }
#pragma unroll
        for (int mt = 0; mt < 2; mt++)
#pragma unroll
            for (int nt = 0; nt < 8; nt++)
#pragma unroll
                for (int rp = 0; rp < 2; rp++)
#pragma unroll
                    for (int e = 0; e < 2; e++) {
                        const float v = fmaxf(acc[mt][nt][rp * 2 + e], 0.f);
                        const int col = wn * 64 + nt * 8 + q * 2 + e;
                        pr[mt][rp] += vrm ? v * mskS[col] : v;
                    }
#pragma unroll
        for (int o = 1; o <= 2; o <<= 1)
#pragma unroll
            for (int mt = 0; mt < 2; mt++)
#pragma unroll
                for (int rp = 0; rp < 2; rp++)
                    pr[mt][rp] += __shfl_xor_sync(0xffffffffu, pr[mt][rp], o);
        if (q == 0) {
#pragma unroll
            for (int mt = 0; mt < 2; mt++)
#pragma unroll
                for (int rp = 0; rp < 2; rp++)
                    rowred[(wm * 32 + mt * 16 + g + rp * 8) * 4 + wn] = pr[mt][rp];
        }
        __syncthreads();
        if (tid < 128) {
            const float s = rowred[tid * 4] + rowred[tid * 4 + 1] +
                            rowred[tid * 4 + 2] + rowred[tid * 4 + 3];
            g_part_m[(((size_t)b * 8 + mtb) * 16 + ntb) * 128 + tid] = s;
        }
    } else {
        float* colred = (float*)dsm;            // [256][4]
        float* avS = (float*)dsm + 1024;        // [128]
        if (tid < 128) avS[tid] = g_avg[b * CH_ + mtb * 128 + tid];
        __syncthreads();
        float pc[8][2];
#pragma unroll
        for (int nt = 0; nt < 8; nt++) { pc[nt][0] = 0.f; pc[nt][1] = 0.f; }
#pragma unroll
        for (int mt = 0; mt < 2; mt++)
#pragma unroll
            for (int rp = 0; rp < 2; rp++) {
                const float av = avS[wm * 32 + mt * 16 + g + rp * 8];
#pragma unroll
                for (int nt = 0; nt < 8; nt++)
#pragma unroll
                    for (int e = 0; e < 2; e++)
                        pc[nt][e] += av * fmaxf(acc[mt][nt][rp * 2 + e], 0.f);
            }
#pragma unroll
        for (int o = 4; o <= 16; o <<= 1)
#pragma unroll
            for (int nt = 0; nt < 8; nt++)
#pragma unroll
                for (int e = 0; e < 2; e++)
                    pc[nt][e] += __shfl_xor_sync(0xffffffffu, pc[nt][e], o);
        if (g == 0) {
#pragma unroll
            for (int nt = 0; nt < 8; nt++)
#pragma unroll
                for (int e = 0; e < 2; e++)
                    colred[(wn * 64 + nt * 8 + q * 2 + e) * 4 + wm] = pc[nt][e];
        }
        __syncthreads();
        if (tid < 256) {
            const float s = colred[tid * 4] + colred[tid * 4 + 1] +
                            colred[tid * 4 + 2] + colred[tid * 4 + 3];
            g_part_n[(((size_t)b * 16 + ntb) * 4 + mtb) * 256 + tid] = s;
        }
    }
}

// deterministic reduce of part_n + sigmoid
__global__ void reduce_n2() {
    const int i = blockIdx.x * 256 + threadIdx.x;  // 65536
    const int b = i >> 12, n = i & 4095;
    const float* p = g_part_n + (((size_t)b * 16 + (n >> 8)) * 4) * 256 + (n & 255);
    const float s = p[0] + p[256] + p[512] + p[768];
    g_chattn[i] = 1.f / (1.f + __expf(-s));
}

// ---------------- final elementwise combine ----------------
__global__ void combine(const float* __restrict__ x, float* __restrict__ out) {
    const size_t i = (size_t)blockIdx.x * blockDim.x + threadIdx.x;
    const int n4 = (int)(i & 1023);
    const int c  = (int)((i >> 10) & 1023);
    const int b  = (int)(i >> 20);
    const float4 xv = ((const float4*)x)[i];
    const float4 ch = ((const float4*)g_chattn)[(size_t)b * 1024 + n4];
    const float sp = g_spatial[b * CH_ + (c & (CH_ - 1))];
    float4 o;
    if (c < CH_) {
        o.x = fmaf(xv.x, sp * ch.x, xv.x);
        o.y = fmaf(xv.y, sp * ch.y, xv.y);
        o.z = fmaf(xv.z, sp * ch.z, xv.z);
        o.w = fmaf(xv.w, sp * ch.w, xv.w);
    } else {
        o.x = fmaf(xv.x, sp + ch.x, xv.x);
        o.y = fmaf(xv.y, sp + ch.y, xv.y);
        o.z = fmaf(xv.z, sp + ch.z, xv.z);
        o.w = fmaf(xv.w, sp + ch.w, xv.w);
    }
    ((float4*)out)[i] = o;
}

// ---------------- launch ----------------
extern "C" void kernel_launch(void* const* d_in, const int* in_sizes, int n_in,
                              void* d_out, int out_size) {
    const float* x    = (const float*)d_in[0];
    const float* w_qr = (const float*)d_in[1];
    const float* w_vr = (const float*)d_in[2];
    const float* w_ql = (const float*)d_in[3];
    const float* w_vl = (const float*)d_in[4];
    float* out = (float*)d_out;

    cudaFuncSetAttribute(hmma_gemm<0>, cudaFuncAttributeMaxDynamicSharedMemorySize, SMEM_GEMM);
    cudaFuncSetAttribute(hmma_gemm<1>, cudaFuncAttributeMaxDynamicSharedMemorySize, SMEM_GEMM);

    convert_w<<<1536, 512>>>(w_ql, w_vr, w_vl);                        // 1
    transpose_x<<<dim3(HW_ / 32, C_ / 128, B_), 256>>>(x, w_qr);       // 2
    softmax_hw<<<B_, 1024>>>();                                        // 3
    hmma_gemm<0><<<dim3(16, 8, B_), 512, SMEM_GEMM>>>();               // 4  <- ncu -s 5 target
    fuse_mid<<<B_, 512>>>();                                           // 5
    hmma_gemm<1><<<dim3(16, 4, B_), 512, SMEM_GEMM>>>();               // 6
    reduce_n2<<<256, 256>>>();                                         // 7
    combine<<<(B_ * C_ * HW_ / 4) / 256, 256>>>(x, out);               // 8
}

// round 6
// speedup vs baseline: 4.8465x; 1.0478x over previous
#include <cuda_runtime.h>
#include <cuda_bf16.h>
#include <stdint.h>
#include <math.h>

#define B_  16
#define C_  1024
#define CH_ 512
#define HW_ 4096

// ---------------- device scratch ----------------
__device__ __align__(16) __nv_bfloat16 g_wbf[1536 * 1024];              // stacked [ql;vr;vl] bf16
__device__ __align__(16) __nv_bfloat16 g_xbf[(size_t)B_ * HW_ * 1024];  // xT[b][n][k] bf16
__device__ __align__(16) float g_qrp[B_ * 8 * HW_];  // qr partials per 128-channel block
__device__ __align__(16) float g_mask[B_ * HW_];
__device__ __align__(16) float g_avg[B_ * CH_];
__device__ __align__(16) float g_spatial[B_ * CH_];
__device__ __align__(16) float g_chattn[B_ * HW_];
__device__ __align__(16) float g_part_m[B_ * 8 * 16 * 128];  // (b, mtile8, ntile16, row128)
__device__ __align__(16) float g_part_n[B_ * 16 * 4 * 256];  // (b, ntile16, mtile4, col256)

// ---------------- helpers ----------------
__device__ __forceinline__ uint32_t s2u(const void* p) {
    uint32_t a;
    asm("{ .reg .u64 t; cvta.to.shared.u64 t, %1; cvt.u32.u64 %0, t; }" : "=r"(a) : "l"(p));
    return a;
}
__device__ __forceinline__ void cp16(uint32_t dst, const void* src) {
    asm volatile("cp.async.cg.shared.global [%0], [%1], 16;" :: "r"(dst), "l"(src) : "memory");
}
#define CP_COMMIT() asm volatile("cp.async.commit_group;" ::: "memory")
#define CP_WAIT(n)  asm volatile("cp.async.wait_group %0;" :: "n"(n) : "memory")

__device__ __forceinline__ void ldsm4(uint32_t* r, uint32_t addr) {
    asm volatile("ldmatrix.sync.aligned.m8n8.x4.shared.b16 {%0,%1,%2,%3}, [%4];"
                 : "=r"(r[0]), "=r"(r[1]), "=r"(r[2]), "=r"(r[3]) : "r"(addr));
}

__device__ __forceinline__ void mma16816(float* d, uint32_t a0, uint32_t a1, uint32_t a2,
                                         uint32_t a3, uint32_t b0, uint32_t b1) {
    asm volatile(
        "mma.sync.aligned.m16n8k16.row.col.f32.bf16.bf16.f32 "
        "{%0,%1,%2,%3}, {%4,%5,%6,%7}, {%8,%9}, {%0,%1,%2,%3};"
        : "+f"(d[0]), "+f"(d[1]), "+f"(d[2]), "+f"(d[3])
        : "r"(a0), "r"(a1), "r"(a2), "r"(a3), "r"(b0), "r"(b1));
}

// ---------------- conversion kernels ----------------
__global__ void convert_w(const float* __restrict__ wql, const float* __restrict__ wvr,
                          const float* __restrict__ wvl) {
    const int i = blockIdx.x * 512 + threadIdx.x;  // 786432 pairs
    const int m = i >> 9;
    const int k = (i & 511) * 2;
    const float* src = (m < 512) ? (wql + (size_t)m * 1024)
                                 : ((m < 1024) ? (wvr + (size_t)(m - 512) * 1024)
                                               : (wvl + (size_t)(m - 1024) * 1024));
    __nv_bfloat162 h = __floats2bfloat162_rn(src[k], src[k + 1]);
    ((uint32_t*)g_wbf)[i] = *reinterpret_cast<uint32_t*>(&h);
}

// x[b][c][n] fp32 -> xT[b][n][c] bf16, plus fused partial qr dot product.
__global__ void transpose_x(const float* __restrict__ x, const float* __restrict__ wqr) {
    __shared__ float s[32][129];
    const int tid = threadIdx.x;
    const int n0 = blockIdx.x * 32, c0 = blockIdx.y * 128, b = blockIdx.z;
#pragma unroll
    for (int r = 0; r < 16; r++) {
        const int ci = (tid >> 5) + r * 8;
        const int ni = tid & 31;
        s[ni][ci] = x[((size_t)(b * C_ + c0 + ci)) * HW_ + n0 + ni];
    }
    __syncthreads();
#pragma unroll
    for (int r = 0; r < 8; r++) {
        const int ni = (tid >> 6) + r * 4;
        const int u = tid & 63;
        __nv_bfloat162 h = __floats2bfloat162_rn(s[ni][u * 2], s[ni][u * 2 + 1]);
        ((uint32_t*)g_xbf)[((size_t)(b * HW_ + n0 + ni)) * 512 + (c0 >> 1) + u] =
            *reinterpret_cast<uint32_t*>(&h);
    }
    {
        const int ni = tid >> 3, lg = tid & 7;
        float p = 0.f;
#pragma unroll
        for (int r = 0; r < 16; r++) {
            const int ci = lg * 16 + r;
            p = fmaf(wqr[c0 + ci], s[ni][ci], p);
        }
#pragma unroll
        for (int o = 1; o <= 4; o <<= 1) p += __shfl_xor_sync(0xffffffffu, p, o);
        if (lg == 0) g_qrp[((size_t)b * 8 + blockIdx.y) * HW_ + n0 + ni] = p;
    }
}

// ---------------- small reductions ----------------
template <int NW>
__device__ __forceinline__ float blockSum(float v, float* sh, float* bc) {
#pragma unroll
    for (int o = 16; o > 0; o >>= 1) v += __shfl_xor_sync(0xffffffffu, v, o);
    int t = threadIdx.x;
    if ((t & 31) == 0) sh[t >> 5] = v;
    __syncthreads();
    if (t < 32) {
        float w = (t < NW) ? sh[t] : 0.f;
#pragma unroll
        for (int o = 16; o > 0; o >>= 1) w += __shfl_xor_sync(0xffffffffu, w, o);
        if (t == 0) *bc = w;
    }
    __syncthreads();
    return *bc;
}
template <int NW>
__device__ __forceinline__ float blockMax(float v, float* sh, float* bc) {
#pragma unroll
    for (int o = 16; o > 0; o >>= 1) v = fmaxf(v, __shfl_xor_sync(0xffffffffu, v, o));
    int t = threadIdx.x;
    if ((t & 31) == 0) sh[t >> 5] = v;
    __syncthreads();
    if (t < 32) {
        float w = (t < NW) ? sh[t] : -3.4e38f;
#pragma unroll
        for (int o = 16; o > 0; o >>= 1) w = fmaxf(w, __shfl_xor_sync(0xffffffffu, w, o));
        if (t == 0) *bc = w;
    }
    __syncthreads();
    return *bc;
}

// sum qr partials -> relu -> softmax over hw
__global__ void softmax_hw() {
    __shared__ float sh[32];
    __shared__ float bc;
    const int b = blockIdx.x, t = threadIdx.x;
    float v[4];
#pragma unroll
    for (int j = 0; j < 4; j++) {
        const int n = t + j * 1024;
        float s = 0.f;
#pragma unroll
        for (int cb = 0; cb < 8; cb++) s += g_qrp[((size_t)b * 8 + cb) * HW_ + n];
        v[j] = fmaxf(s, 0.f);
    }
    float m = fmaxf(fmaxf(v[0], v[1]), fmaxf(v[2], v[3]));
    const float bm = blockMax<32>(m, sh, &bc);
    float e[4], s = 0.f;
#pragma unroll
    for (int j = 0; j < 4; j++) { e[j] = __expf(v[j] - bm); s += e[j]; }
    const float bs = blockSum<32>(s, sh, &bc);
    const float inv = 1.f / bs;
#pragma unroll
    for (int j = 0; j < 4; j++) g_mask[b * HW_ + t + j * 1024] = e[j] * inv;
}

// fused: reduce part_m -> gx/ctx -> softmax(avg) + layernorm+sigmoid(spatial)
__global__ void fuse_mid() {
    __shared__ float sh[16];
    __shared__ float bc;
    const int b = blockIdx.x, t = threadIdx.x;  // 512 threads
    float s0 = 0.f, s1 = 0.f;
    {
        const int m = t;
        const float* p = g_part_m + (((size_t)b * 8 + (m >> 7)) * 16) * 128 + (m & 127);
#pragma unroll
        for (int nt = 0; nt < 16; nt++) s0 += p[nt * 128];
    }
    {
        const int m = t + 512;
        const float* p = g_part_m + (((size_t)b * 8 + (m >> 7)) * 16) * 128 + (m & 127);
#pragma unroll
        for (int nt = 0; nt < 16; nt++) s1 += p[nt * 128];
    }
    const float v = s0 * (1.f / (float)HW_);
    const float bm = blockMax<16>(v, sh, &bc);
    const float e = __expf(v - bm);
    const float bs = blockSum<16>(e, sh, &bc);
    g_avg[b * CH_ + t] = e / bs;
    const float mean = blockSum<16>(s1, sh, &bc) * (1.f / (float)CH_);
    const float d = s1 - mean;
    const float var = blockSum<16>(d * d, sh, &bc) * (1.f / (float)CH_);
    const float z = d * rsqrtf(var + 1e-5f);
    g_spatial[b * CH_ + t] = 1.f / (1.f + __expf(-z));
}

// ---------------- HMMA GEMM with fused reduction epilogues ----------------
// Block tile M=128, N=256, K=32. 3-stage cp.async pipeline. 16 warps, warp tile 32x64.
// Fragments via ldmatrix.x4, double-buffered across the two k16 sub-steps.
// smem: 3 stages x (A 128x40 + B 256x40) bf16 = 3 x 30720B = 92160B.
#define SMEM_GEMM 92160

__device__ __forceinline__ void load_tile(uint32_t sA, uint32_t sB,
                                          const __nv_bfloat16* __restrict__ Wp,
                                          const __nv_bfloat16* __restrict__ Xp,
                                          int kb, int stage, int lrow, int lseg) {
    cp16(sA + (uint32_t)stage * 10240u + (uint32_t)(lrow * 40 + lseg * 8) * 2u,
         Wp + (size_t)lrow * 1024 + kb * 32 + lseg * 8);
#pragma unroll
    for (int i = 0; i < 2; i++) {
        const int row = lrow + i * 128;
        cp16(sB + (uint32_t)stage * 20480u + (uint32_t)(row * 40 + lseg * 8) * 2u,
             Xp + (size_t)row * 1024 + kb * 32 + lseg * 8);
    }
    CP_COMMIT();
}

template <int PHASE>
__global__ __launch_bounds__(512, 1) void hmma_gemm() {
    extern __shared__ char dsm[];
    const uint32_t sA = s2u(dsm), sB = sA + 30720u;

    const int tid = threadIdx.x, lid = tid & 31, wid = tid >> 5;
    const int wm = wid & 3, wn = wid >> 2;      // 4 x 4 warp grid
    const int g = lid >> 2, q = lid & 3;
    const int b = blockIdx.z, ntb = blockIdx.x, mtb = blockIdx.y;
    const int n0 = ntb * 256;
    const int m0 = (PHASE == 0 ? 0 : 1024) + mtb * 128;
    const __nv_bfloat16* Wp = g_wbf + (size_t)m0 * 1024;
    const __nv_bfloat16* Xp = g_xbf + ((size_t)b * HW_ + n0) * 1024;

    const int lrow = tid >> 2, lseg = tid & 3;  // 128 rows x 4 segs

    // ldmatrix lane address components (byte offsets relative to stage base)
    const int alane = lid & 15;
    const int ahalf = (lid >> 4) << 3;
    const int brw = (lid & 7) + ((lid >> 4) << 3);
    const int bhalf = ((lid >> 3) & 1) << 3;
    uint32_t aob[2], bob[4];
#pragma unroll
    for (int mt = 0; mt < 2; mt++)
        aob[mt] = (uint32_t)((wm * 32 + mt * 16 + alane) * 40 + ahalf) * 2u;
#pragma unroll
    for (int p = 0; p < 4; p++)
        bob[p] = (uint32_t)((wn * 64 + p * 16 + brw) * 40 + bhalf) * 2u;

    float acc[2][8][4];
#pragma unroll
    for (int mt = 0; mt < 2; mt++)
#pragma unroll
        for (int nt = 0; nt < 8; nt++)
#pragma unroll
            for (int e = 0; e < 4; e++) acc[mt][nt][e] = 0.f;

    load_tile(sA, sB, Wp, Xp, 0, 0, lrow, lseg);
    load_tile(sA, sB, Wp, Xp, 1, 1, lrow, lseg);

    int cs = 0, ls = 2;
    for (int it = 0; it < 32; ++it) {
        if (it < 31) { CP_WAIT(1); } else { CP_WAIT(0); }
        __syncthreads();
        if (it + 2 < 32) load_tile(sA, sB, Wp, Xp, it + 2, ls, lrow, lseg);

        const uint32_t Ac = sA + (uint32_t)cs * 10240u;
        const uint32_t Bc = sB + (uint32_t)cs * 20480u;

        uint32_t af[2][2][4], bfr[2][16];
#pragma unroll
        for (int st = 0; st < 2; st++) {
#pragma unroll
            for (int mt = 0; mt < 2; mt++) ldsm4(af[st][mt], Ac + aob[mt] + st * 32);
#pragma unroll
            for (int p = 0; p < 4; p++) ldsm4(&bfr[st][p * 4], Bc + bob[p] + st * 32);
        }
#pragma unroll
        for (int st = 0; st < 2; st++)
#pragma unroll
            for (int mt = 0; mt < 2; mt++)
#pragma unroll
                for (int nt = 0; nt < 8; nt++) {
                    const int bi = (nt >> 1) * 4 + (nt & 1) * 2;
                    mma16816(acc[mt][nt], af[st][mt][0], af[st][mt][1], af[st][mt][2],
                             af[st][mt][3], bfr[st][bi], bfr[st][bi + 1]);
                }

        cs = (cs == 2) ? 0 : cs + 1;
        ls = (ls == 2) ? 0 : ls + 1;
    }
    __syncthreads();

    // ---------------- fused reduction epilogue ----------------
    if (PHASE == 0) {
        float* rowred = (float*)dsm;            // [128][4]
        float* mskS = (float*)dsm + 1024;       // [256]
        const bool vrm = (mtb >= 4);
        if (vrm && tid < 256) mskS[tid] = g_mask[b * HW_ + n0 + tid];
        __syncthreads();
        float pr[2][2];
#pragma unroll
        for (int mt = 0; mt < 2; mt++) { pr[mt][0] = 0.f; pr[mt][1] = 0.f; }
#pragma unroll
        for (int mt = 0; mt < 2; mt++)
#pragma unroll
            for (int nt = 0; nt < 8; nt++)
#pragma unroll
                for (int rp = 0; rp < 2; rp++)
#pragma unroll
                    for (int e = 0; e < 2; e++) {
                        const float v = fmaxf(acc[mt][nt][rp * 2 + e], 0.f);
                        const int col = wn * 64 + nt * 8 + q * 2 + e;
                        pr[mt][rp] += vrm ? v * mskS[col] : v;
                    }
#pragma unroll
        for (int o = 1; o <= 2; o <<= 1)
#pragma unroll
            for (int mt = 0; mt < 2; mt++)
#pragma unroll
                for (int rp = 0; rp < 2; rp++)
                    pr[mt][rp] += __shfl_xor_sync(0xffffffffu, pr[mt][rp], o);
        if (q == 0) {
#pragma unroll
            for (int mt = 0; mt < 2; mt++)
#pragma unroll
                for (int rp = 0; rp < 2; rp++)
                    rowred[(wm * 32 + mt * 16 + g + rp * 8) * 4 + wn] = pr[mt][rp];
        }
        __syncthreads();
        if (tid < 128) {
            const float s = rowred[tid * 4] + rowred[tid * 4 + 1] +
                            rowred[tid * 4 + 2] + rowred[tid * 4 + 3];
            g_part_m[(((size_t)b * 8 + mtb) * 16 + ntb) * 128 + tid] = s;
        }
    } else {
        float* colred = (float*)dsm;            // [256][4]
        float* avS = (float*)dsm + 1024;        // [128]
        if (tid < 128) avS[tid] = g_avg[b * CH_ + mtb * 128 + tid];
        __syncthreads();
        float pc[8][2];
#pragma unroll
        for (int nt = 0; nt < 8; nt++) { pc[nt][0] = 0.f; pc[nt][1] = 0.f; }
#pragma unroll
        for (int mt = 0; mt < 2; mt++)
#pragma unroll
            for (int rp = 0; rp < 2; rp++) {
                const float av = avS[wm * 32 + mt * 16 + g + rp * 8];
#pragma unroll
                for (int nt = 0; nt < 8; nt++)
#pragma unroll
                    for (int e = 0; e < 2; e++)
                        pc[nt][e] += av * fmaxf(acc[mt][nt][rp * 2 + e], 0.f);
            }
#pragma unroll
        for (int o = 4; o <= 16; o <<= 1)
#pragma unroll
            for (int nt = 0; nt < 8; nt++)
#pragma unroll
                for (int e = 0; e < 2; e++)
                    pc[nt][e] += __shfl_xor_sync(0xffffffffu, pc[nt][e], o);
        if (g == 0) {
#pragma unroll
            for (int nt = 0; nt < 8; nt++)
#pragma unroll
                for (int e = 0; e < 2; e++)
                    colred[(wn * 64 + nt * 8 + q * 2 + e) * 4 + wm] = pc[nt][e];
        }
        __syncthreads();
        if (tid < 256) {
            const float s = colred[tid * 4] + colred[tid * 4 + 1] +
                            colred[tid * 4 + 2] + colred[tid * 4 + 3];
            g_part_n[(((size_t)b * 16 + ntb) * 4 + mtb) * 256 + tid] = s;
        }
    }
}

// deterministic reduce of part_n + sigmoid
__global__ void reduce_n2() {
    const int i = blockIdx.x * 256 + threadIdx.x;  // 65536
    const int b = i >> 12, n = i & 4095;
    const float* p = g_part_n + (((size_t)b * 16 + (n >> 8)) * 4) * 256 + (n & 255);
    const float s = p[0] + p[256] + p[512] + p[768];
    g_chattn[i] = 1.f / (1.f + __expf(-s));
}

// ---------------- final elementwise combine ----------------
__global__ void combine(const float* __restrict__ x, float* __restrict__ out) {
    const size_t i = (size_t)blockIdx.x * blockDim.x + threadIdx.x;
    const int n4 = (int)(i & 1023);
    const int c  = (int)((i >> 10) & 1023);
    const int b  = (int)(i >> 20);
    const float4 xv = ((const float4*)x)[i];
    const float4 ch = ((const float4*)g_chattn)[(size_t)b * 1024 + n4];
    const float sp = g_spatial[b * CH_ + (c & (CH_ - 1))];
    float4 o;
    if (c < CH_) {
        o.x = fmaf(xv.x, sp * ch.x, xv.x);
        o.y = fmaf(xv.y, sp * ch.y, xv.y);
        o.z = fmaf(xv.z, sp * ch.z, xv.z);
        o.w = fmaf(xv.w, sp * ch.w, xv.w);
    } else {
        o.x = fmaf(xv.x, sp + ch.x, xv.x);
        o.y = fmaf(xv.y, sp + ch.y, xv.y);
        o.z = fmaf(xv.z, sp + ch.z, xv.z);
        o.w = fmaf(xv.w, sp + ch.w, xv.w);
    }
    ((float4*)out)[i] = o;
}

// ---------------- launch ----------------
extern "C" void kernel_launch(void* const* d_in, const int* in_sizes, int n_in,
                              void* d_out, int out_size) {
    const float* x    = (const float*)d_in[0];
    const float* w_qr = (const float*)d_in[1];
    const float* w_vr = (const float*)d_in[2];
    const float* w_ql = (const float*)d_in[3];
    const float* w_vl = (const float*)d_in[4];
    float* out = (float*)d_out;

    cudaFuncSetAttribute(hmma_gemm<0>, cudaFuncAttributeMaxDynamicSharedMemorySize, SMEM_GEMM);
    cudaFuncSetAttribute(hmma_gemm<1>, cudaFuncAttributeMaxDynamicSharedMemorySize, SMEM_GEMM);

    convert_w<<<1536, 512>>>(w_ql, w_vr, w_vl);                        // 1
    transpose_x<<<dim3(HW_ / 32, C_ / 128, B_), 256>>>(x, w_qr);       // 2
    softmax_hw<<<B_, 1024>>>();                                        // 3
    hmma_gemm<0><<<dim3(16, 8, B_), 512, SMEM_GEMM>>>();               // 4  <- ncu -s 5 target
    fuse_mid<<<B_, 512>>>();                                           // 5
    hmma_gemm<1><<<dim3(16, 4, B_), 512, SMEM_GEMM>>>();               // 6
    reduce_n2<<<256, 256>>>();                                         // 7
    combine<<<(B_ * C_ * HW_ / 4) / 256, 256>>>(x, out);               // 8
}

// round 7
// speedup vs baseline: 5.0742x; 1.0470x over previous
#include <cuda_runtime.h>
#include <cuda_bf16.h>
#include <stdint.h>
#include <math.h>

#define B_  16
#define C_  1024
#define CH_ 512
#define HW_ 4096

// ---------------- device scratch ----------------
__device__ __align__(16) __nv_bfloat16 g_wbf[1536 * 1024];              // stacked [ql;vr;vl] bf16
__device__ __align__(16) __nv_bfloat16 g_xbf[(size_t)B_ * HW_ * 1024];  // xT[b][n][k] bf16
__device__ __align__(16) float g_qrp[B_ * 8 * HW_];  // qr partials per 128-channel block
__device__ __align__(16) float g_mask[B_ * HW_];
__device__ __align__(16) float g_avg[B_ * CH_];
__device__ __align__(16) float g_spatial[B_ * CH_];
__device__ __align__(16) float g_chattn[B_ * HW_];
__device__ __align__(16) float g_part_m[B_ * 8 * 32 * 128];  // (b, mtile8, ntile32, row128)
__device__ __align__(16) float g_part_n[B_ * 32 * 4 * 128];  // (b, ntile32, mtile4, col128)

// ---------------- helpers ----------------
__device__ __forceinline__ uint32_t s2u(const void* p) {
    uint32_t a;
    asm("{ .reg .u64 t; cvta.to.shared.u64 t, %1; cvt.u32.u64 %0, t; }" : "=r"(a) : "l"(p));
    return a;
}
__device__ __forceinline__ void cp16(uint32_t dst, const void* src) {
    asm volatile("cp.async.cg.shared.global [%0], [%1], 16;" :: "r"(dst), "l"(src) : "memory");
}
#define CP_COMMIT() asm volatile("cp.async.commit_group;" ::: "memory")
#define CP_WAIT(n)  asm volatile("cp.async.wait_group %0;" :: "n"(n) : "memory")

__device__ __forceinline__ void ldsm4(uint32_t* r, uint32_t addr) {
    asm volatile("ldmatrix.sync.aligned.m8n8.x4.shared.b16 {%0,%1,%2,%3}, [%4];"
                 : "=r"(r[0]), "=r"(r[1]), "=r"(r[2]), "=r"(r[3]) : "r"(addr));
}

__device__ __forceinline__ void mma16816(float* d, uint32_t a0, uint32_t a1, uint32_t a2,
                                         uint32_t a3, uint32_t b0, uint32_t b1) {
    asm volatile(
        "mma.sync.aligned.m16n8k16.row.col.f32.bf16.bf16.f32 "
        "{%0,%1,%2,%3}, {%4,%5,%6,%7}, {%8,%9}, {%0,%1,%2,%3};"
        : "+f"(d[0]), "+f"(d[1]), "+f"(d[2]), "+f"(d[3])
        : "r"(a0), "r"(a1), "r"(a2), "r"(a3), "r"(b0), "r"(b1));
}

// ---------------- conversion kernels ----------------
__global__ void convert_w(const float* __restrict__ wql, const float* __restrict__ wvr,
                          const float* __restrict__ wvl) {
    const int i = blockIdx.x * 512 + threadIdx.x;  // 786432 pairs
    const int m = i >> 9;
    const int k = (i & 511) * 2;
    const float* src = (m < 512) ? (wql + (size_t)m * 1024)
                                 : ((m < 1024) ? (wvr + (size_t)(m - 512) * 1024)
                                               : (wvl + (size_t)(m - 1024) * 1024));
    __nv_bfloat162 h = __floats2bfloat162_rn(src[k], src[k + 1]);
    ((uint32_t*)g_wbf)[i] = *reinterpret_cast<uint32_t*>(&h);
}

// x[b][c][n] fp32 -> xT[b][n][c] bf16, plus fused partial qr dot product.
__global__ void transpose_x(const float* __restrict__ x, const float* __restrict__ wqr) {
    __shared__ float s[32][129];
    const int tid = threadIdx.x;
    const int n0 = blockIdx.x * 32, c0 = blockIdx.y * 128, b = blockIdx.z;
#pragma unroll
    for (int r = 0; r < 16; r++) {
        const int ci = (tid >> 5) + r * 8;
        const int ni = tid & 31;
        s[ni][ci] = x[((size_t)(b * C_ + c0 + ci)) * HW_ + n0 + ni];
    }
    __syncthreads();
#pragma unroll
    for (int r = 0; r < 8; r++) {
        const int ni = (tid >> 6) + r * 4;
        const int u = tid & 63;
        __nv_bfloat162 h = __floats2bfloat162_rn(s[ni][u * 2], s[ni][u * 2 + 1]);
        ((uint32_t*)g_xbf)[((size_t)(b * HW_ + n0 + ni)) * 512 + (c0 >> 1) + u] =
            *reinterpret_cast<uint32_t*>(&h);
    }
    {
        const int ni = tid >> 3, lg = tid & 7;
        float p = 0.f;
#pragma unroll
        for (int r = 0; r < 16; r++) {
            const int ci = lg * 16 + r;
            p = fmaf(wqr[c0 + ci], s[ni][ci], p);
        }
#pragma unroll
        for (int o = 1; o <= 4; o <<= 1) p += __shfl_xor_sync(0xffffffffu, p, o);
        if (lg == 0) g_qrp[((size_t)b * 8 + blockIdx.y) * HW_ + n0 + ni] = p;
    }
}

// ---------------- small reductions ----------------
template <int NW>
__device__ __forceinline__ float blockSum(float v, float* sh, float* bc) {
#pragma unroll
    for (int o = 16; o > 0; o >>= 1) v += __shfl_xor_sync(0xffffffffu, v, o);
    int t = threadIdx.x;
    if ((t & 31) == 0) sh[t >> 5] = v;
    __syncthreads();
    if (t < 32) {
        float w = (t < NW) ? sh[t] : 0.f;
#pragma unroll
        for (int o = 16; o > 0; o >>= 1) w += __shfl_xor_sync(0xffffffffu, w, o);
        if (t == 0) *bc = w;
    }
    __syncthreads();
    return *bc;
}
template <int NW>
__device__ __forceinline__ float blockMax(float v, float* sh, float* bc) {
#pragma unroll
    for (int o = 16; o > 0; o >>= 1) v = fmaxf(v, __shfl_xor_sync(0xffffffffu, v, o));
    int t = threadIdx.x;
    if ((t & 31) == 0) sh[t >> 5] = v;
    __syncthreads();
    if (t < 32) {
        float w = (t < NW) ? sh[t] : -3.4e38f;
#pragma unroll
        for (int o = 16; o > 0; o >>= 1) w = fmaxf(w, __shfl_xor_sync(0xffffffffu, w, o));
        if (t == 0) *bc = w;
    }
    __syncthreads();
    return *bc;
}

// sum qr partials -> relu -> softmax over hw
__global__ void softmax_hw() {
    __shared__ float sh[32];
    __shared__ float bc;
    const int b = blockIdx.x, t = threadIdx.x;
    float v[4];
#pragma unroll
    for (int j = 0; j < 4; j++) {
        const int n = t + j * 1024;
        float s = 0.f;
#pragma unroll
        for (int cb = 0; cb < 8; cb++) s += g_qrp[((size_t)b * 8 + cb) * HW_ + n];
        v[j] = fmaxf(s, 0.f);
    }
    float m = fmaxf(fmaxf(v[0], v[1]), fmaxf(v[2], v[3]));
    const float bm = blockMax<32>(m, sh, &bc);
    float e[4], s = 0.f;
#pragma unroll
    for (int j = 0; j < 4; j++) { e[j] = __expf(v[j] - bm); s += e[j]; }
    const float bs = blockSum<32>(s, sh, &bc);
    const float inv = 1.f / bs;
#pragma unroll
    for (int j = 0; j < 4; j++) g_mask[b * HW_ + t + j * 1024] = e[j] * inv;
}

// fused: reduce part_m -> gx/ctx -> softmax(avg) + layernorm+sigmoid(spatial)
__global__ void fuse_mid() {
    __shared__ float sh[16];
    __shared__ float bc;
    const int b = blockIdx.x, t = threadIdx.x;  // 512 threads
    float s0 = 0.f, s1 = 0.f;
    {
        const int m = t;
        const float* p = g_part_m + (((size_t)b * 8 + (m >> 7)) * 32) * 128 + (m & 127);
#pragma unroll
        for (int nt = 0; nt < 32; nt++) s0 += p[nt * 128];
    }
    {
        const int m = t + 512;
        const float* p = g_part_m + (((size_t)b * 8 + (m >> 7)) * 32) * 128 + (m & 127);
#pragma unroll
        for (int nt = 0; nt < 32; nt++) s1 += p[nt * 128];
    }
    const float v = s0 * (1.f / (float)HW_);
    const float bm = blockMax<16>(v, sh, &bc);
    const float e = __expf(v - bm);
    const float bs = blockSum<16>(e, sh, &bc);
    g_avg[b * CH_ + t] = e / bs;
    const float mean = blockSum<16>(s1, sh, &bc) * (1.f / (float)CH_);
    const float d = s1 - mean;
    const float var = blockSum<16>(d * d, sh, &bc) * (1.f / (float)CH_);
    const float z = d * rsqrtf(var + 1e-5f);
    g_spatial[b * CH_ + t] = 1.f / (1.f + __expf(-z));
}

// ---------------- HMMA GEMM with fused reduction epilogues ----------------
// Block tile M=128, N=128, K=32. 256 threads (8 warps, 2x4 grid), warp tile 64x32.
// 3-stage cp.async pipeline; 2 CTAs/SM (smem 61440B, regs <=128).
// PHASE 0: mtb 0..7 over stacked [ql;vr]: mtb<4 plain row sums; mtb>=4 mask-weighted.
// PHASE 1: mtb 0..3 over vl; avg-weighted col sums.
#define SMEM_GEMM 61440

__device__ __forceinline__ void load_tile(uint32_t sA, uint32_t sB,
                                          const __nv_bfloat16* __restrict__ Wp,
                                          const __nv_bfloat16* __restrict__ Xp,
                                          int kb, int stage, int lrow, int lseg) {
    cp16(sA + (uint32_t)stage * 10240u + (uint32_t)(lrow * 40 + lseg * 8) * 2u,
         Wp + (size_t)lrow * 1024 + kb * 32 + lseg * 8);
    cp16(sB + (uint32_t)stage * 10240u + (uint32_t)(lrow * 40 + lseg * 8) * 2u,
         Xp + (size_t)lrow * 1024 + kb * 32 + lseg * 8);
    CP_COMMIT();
}

template <int PHASE>
__global__ __launch_bounds__(256, 2) void hmma_gemm() {
    extern __shared__ char dsm[];
    const uint32_t sA = s2u(dsm), sB = sA + 30720u;

    const int tid = threadIdx.x, lid = tid & 31, wid = tid >> 5;
    const int wm = wid & 1, wn = wid >> 1;      // 2 x 4 warp grid: warp tile 64x32
    const int g = lid >> 2, q = lid & 3;
    const int b = blockIdx.z, ntb = blockIdx.x, mtb = blockIdx.y;
    const int n0 = ntb * 128;
    const int m0 = (PHASE == 0 ? 0 : 1024) + mtb * 128;
    const __nv_bfloat16* Wp = g_wbf + (size_t)m0 * 1024;
    const __nv_bfloat16* Xp = g_xbf + ((size_t)b * HW_ + n0) * 1024;

    const int lrow = tid >> 1, lseg = tid & 1;  // 128 rows x 2 segs of 16B (32 bf16 = 4 segs? no: 32 cols = 64B = 4x16B)
    // 128 rows x 32 cols x 2B = 8192B per operand per stage; 256 threads x 16B = 4096B -> 2 cp16 each
    // row = tid>>1 covers 128 rows, seg = (tid&1)*2 + i covers 4 segs of 8 cols

    float acc[4][4][4];
#pragma unroll
    for (int mt = 0; mt < 4; mt++)
#pragma unroll
        for (int nt = 0; nt < 4; nt++)
#pragma unroll
            for (int e = 0; e < 4; e++) acc[mt][nt][e] = 0.f;

    // ldmatrix lane address components
    const int alane = lid & 15;
    const int ahalf = (lid >> 4) << 3;
    const int brw = (lid & 7) + ((lid >> 4) << 3);
    const int bhalf = ((lid >> 3) & 1) << 3;
    uint32_t aob[4], bob[2];
#pragma unroll
    for (int mt = 0; mt < 4; mt++)
        aob[mt] = (uint32_t)((wm * 64 + mt * 16 + alane) * 40 + ahalf) * 2u;
#pragma unroll
    for (int p = 0; p < 2; p++)
        bob[p] = (uint32_t)((wn * 32 + p * 16 + brw) * 40 + bhalf) * 2u;

    // initial loads: each thread does 2 cp16 per operand per stage
#pragma unroll
    for (int st0 = 0; st0 < 2; st0++) {
#pragma unroll
        for (int i = 0; i < 2; i++) {
            const int seg = lseg * 2 + i;
            cp16(sA + (uint32_t)st0 * 10240u + (uint32_t)(lrow * 40 + seg * 8) * 2u,
                 Wp + (size_t)lrow * 1024 + st0 * 32 + seg * 8);
            cp16(sB + (uint32_t)st0 * 10240u + (uint32_t)(lrow * 40 + seg * 8) * 2u,
                 Xp + (size_t)lrow * 1024 + st0 * 32 + seg * 8);
        }
        CP_COMMIT();
    }

    int cs = 0, ls = 2;
    for (int it = 0; it < 32; ++it) {
        if (it < 31) { CP_WAIT(1); } else { CP_WAIT(0); }
        __syncthreads();
        if (it + 2 < 32) {
#pragma unroll
            for (int i = 0; i < 2; i++) {
                const int seg = lseg * 2 + i;
                cp16(sA + (uint32_t)ls * 10240u + (uint32_t)(lrow * 40 + seg * 8) * 2u,
                     Wp + (size_t)lrow * 1024 + (it + 2) * 32 + seg * 8);
                cp16(sB + (uint32_t)ls * 10240u + (uint32_t)(lrow * 40 + seg * 8) * 2u,
                     Xp + (size_t)lrow * 1024 + (it + 2) * 32 + seg * 8);
            }
            CP_COMMIT();
        }

        const uint32_t Ac = sA + (uint32_t)cs * 10240u;
        const uint32_t Bc = sB + (uint32_t)cs * 10240u;
#pragma unroll
        for (int st = 0; st < 2; st++) {
            uint32_t af[4][4], bfr[8];
#pragma unroll
            for (int mt = 0; mt < 4; mt++) ldsm4(af[mt], Ac + aob[mt] + st * 32);
#pragma unroll
            for (int p = 0; p < 2; p++) ldsm4(&bfr[p * 4], Bc + bob[p] + st * 32);
#pragma unroll
            for (int mt = 0; mt < 4; mt++)
#pragma unroll
                for (int nt = 0; nt < 4; nt++) {
                    const int bi = (nt >> 1) * 4 + (nt & 1) * 2;
                    mma16816(acc[mt][nt], af[mt][0], af[mt][1], af[mt][2], af[mt][3],
                             bfr[bi], bfr[bi + 1]);
                }
        }

        cs = (cs == 2) ? 0 : cs + 1;
        ls = (ls == 2) ? 0 : ls + 1;
    }
    __syncthreads();

    // ---------------- fused reduction epilogue ----------------
    if (PHASE == 0) {
        float* rowred = (float*)dsm;            // [128][4]
        float* mskS = (float*)dsm + 512;        // [128]
        const bool vrm = (mtb >= 4);
        if (vrm && tid < 128) mskS[tid] = g_mask[b * HW_ + n0 + tid];
        __syncthreads();
        float pr[4][2];
#pragma unroll
        for (int mt = 0; mt < 4; mt++) { pr[mt][0] = 0.f; pr[mt][1] = 0.f; }
#pragma unroll
        for (int mt = 0; mt < 4; mt++)
#pragma unroll
            for (int nt = 0; nt < 4; nt++)
#pragma unroll
                for (int rp = 0; rp < 2; rp++)
#pragma unroll
                    for (int e = 0; e < 2; e++) {
                        const float v = fmaxf(acc[mt][nt][rp * 2 + e], 0.f);
                        const int col = wn * 32 + nt * 8 + q * 2 + e;
                        pr[mt][rp] += vrm ? v * mskS[col] : v;
                    }
#pragma unroll
        for (int o = 1; o <= 2; o <<= 1)
#pragma unroll
            for (int mt = 0; mt < 4; mt++)
#pragma unroll
                for (int rp = 0; rp < 2; rp++)
                    pr[mt][rp] += __shfl_xor_sync(0xffffffffu, pr[mt][rp], o);
        if (q == 0) {
#pragma unroll
            for (int mt = 0; mt < 4; mt++)
#pragma unroll
                for (int rp = 0; rp < 2; rp++)
                    rowred[(wm * 64 + mt * 16 + g + rp * 8) * 4 + wn] = pr[mt][rp];
        }
        __syncthreads();
        if (tid < 128) {
            const float s = rowred[tid * 4] + rowred[tid * 4 + 1] +
                            rowred[tid * 4 + 2] + rowred[tid * 4 + 3];
            g_part_m[(((size_t)b * 8 + mtb) * 32 + ntb) * 128 + tid] = s;
        }
    } else {
        float* colred = (float*)dsm;            // [128][2]
        float* avS = (float*)dsm + 256;         // [128]
        if (tid < 128) avS[tid] = g_avg[b * CH_ + mtb * 128 + tid];
        __syncthreads();
        float pc[4][2];
#pragma unroll
        for (int nt = 0; nt < 4; nt++) { pc[nt][0] = 0.f; pc[nt][1] = 0.f; }
#pragma unroll
        for (int mt = 0; mt < 4; mt++)
#pragma unroll
            for (int rp = 0; rp < 2; rp++) {
                const float av = avS[wm * 64 + mt * 16 + g + rp * 8];
#pragma unroll
                for (int nt = 0; nt < 4; nt++)
#pragma unroll
                    for (int e = 0; e < 2; e++)
                        pc[nt][e] += av * fmaxf(acc[mt][nt][rp * 2 + e], 0.f);
            }
#pragma unroll
        for (int o = 4; o <= 16; o <<= 1)
#pragma unroll
            for (int nt = 0; nt < 4; nt++)
#pragma unroll
                for (int e = 0; e < 2; e++)
                    pc[nt][e] += __shfl_xor_sync(0xffffffffu, pc[nt][e], o);
        if (g == 0) {
#pragma unroll
            for (int nt = 0; nt < 4; nt++)
#pragma unroll
                for (int e = 0; e < 2; e++)
                    colred[(wn * 32 + nt * 8 + q * 2 + e) * 2 + wm] = pc[nt][e];
        }
        __syncthreads();
        if (tid < 128) {
            const float s = colred[tid * 2] + colred[tid * 2 + 1];
            g_part_n[(((size_t)b * 32 + ntb) * 4 + mtb) * 128 + tid] = s;
        }
    }
}

// deterministic reduce of part_n + sigmoid
__global__ void reduce_n2() {
    const int i = blockIdx.x * 256 + threadIdx.x;  // 65536
    const int b = i >> 12, n = i & 4095;
    const float* p = g_part_n + (((size_t)b * 32 + (n >> 7)) * 4) * 128 + (n & 127);
    const float s = p[0] + p[128] + p[256] + p[384];
    g_chattn[i] = 1.f / (1.f + __expf(-s));
}

// ---------------- final elementwise combine ----------------
__global__ void combine(const float* __restrict__ x, float* __restrict__ out) {
    const size_t i = (size_t)blockIdx.x * blockDim.x + threadIdx.x;
    const int n4 = (int)(i & 1023);
    const int c  = (int)((i >> 10) & 1023);
    const int b  = (int)(i >> 20);
    const float4 xv = ((const float4*)x)[i];
    const float4 ch = ((const float4*)g_chattn)[(size_t)b * 1024 + n4];
    const float sp = g_spatial[b * CH_ + (c & (CH_ - 1))];
    float4 o;
    if (c < CH_) {
        o.x = fmaf(xv.x, sp * ch.x, xv.x);
        o.y = fmaf(xv.y, sp * ch.y, xv.y);
        o.z = fmaf(xv.z, sp * ch.z, xv.z);
        o.w = fmaf(xv.w, sp * ch.w, xv.w);
    } else {
        o.x = fmaf(xv.x, sp + ch.x, xv.x);
        o.y = fmaf(xv.y, sp + ch.y, xv.y);
        o.z = fmaf(xv.z, sp + ch.z, xv.z);
        o.w = fmaf(xv.w, sp + ch.w, xv.w);
    }
    ((float4*)out)[i] = o;
}

// ---------------- launch ----------------
extern "C" void kernel_launch(void* const* d_in, const int* in_sizes, int n_in,
                              void* d_out, int out_size) {
    const float* x    = (const float*)d_in[0];
    const float* w_qr = (const float*)d_in[1];
    const float* w_vr = (const float*)d_in[2];
    const float* w_ql = (const float*)d_in[3];
    const float* w_vl = (const float*)d_in[4];
    float* out = (float*)d_out;

    cudaFuncSetAttribute(hmma_gemm<0>, cudaFuncAttributeMaxDynamicSharedMemorySize, SMEM_GEMM);
    cudaFuncSetAttribute(hmma_gemm<1>, cudaFuncAttributeMaxDynamicSharedMemorySize, SMEM_GEMM);

    convert_w<<<1536, 512>>>(w_ql, w_vr, w_vl);                        // 1
    transpose_x<<<dim3(HW_ / 32, C_ / 128, B_), 256>>>(x, w_qr);       // 2
    softmax_hw<<<B_, 1024>>>();                                        // 3
    hmma_gemm<0><<<dim3(32, 8, B_), 256, SMEM_GEMM>>>();               // 4  <- ncu target
    fuse_mid<<<B_, 512>>>();                                           // 5
    hmma_gemm<1><<<dim3(32, 4, B_), 256, SMEM_GEMM>>>();               // 6
    reduce_n2<<<256, 256>>>();                                         // 7
    combine<<<(B_ * C_ * HW_ / 4) / 256, 256>>>(x, out);               // 8
}